// round 1
// baseline (speedup 1.0000x reference)
#include <cuda_runtime.h>
#include <math.h>

#define BB 2
#define SS 2048
#define DD 1024
#define HH 16
#define HDim 64
#define NH (BB*HH)   // 32 (b,h) pairs

// Scratch (allocation-free): Q/K/V in (B,H,S,HD) layout, attn_output in (B,S,D)
__device__ float g_q[(size_t)NH * SS * HDim];
__device__ float g_k[(size_t)NH * SS * HDim];
__device__ float g_v[(size_t)NH * SS * HDim];
__device__ float g_ao[(size_t)BB * SS * DD];

// ---------------------------------------------------------------------------
// Projection GEMM: Y = X @ W^T + bias
//   X: (M=4096, K=1024) row-major, W: (N=1024, K=1024) row-major
//   SPLIT=true  -> write to (B,H,S,HD) head layout
//   SPLIT=false -> write row-major (M, N)
// 64x64 tile, BK=16, 256 threads, 4x4 per thread.
// ---------------------------------------------------------------------------
template <bool SPLIT>
__global__ __launch_bounds__(256) void proj_kernel(
    const float* __restrict__ X, const float* __restrict__ W,
    const float* __restrict__ bias, float* __restrict__ Y)
{
    const int K = DD;
    __shared__ float As[16][65];   // [k][m], padded: conflict-free stores
    __shared__ float Bs[16][65];   // [k][n]
    const int tid = threadIdx.x;
    const int tx = tid & 15, ty = tid >> 4;
    const int m0 = blockIdx.y << 6, n0 = blockIdx.x << 6;
    const int c = tid & 15, r = tid >> 4;

    float acc[4][4] = {};

    for (int k0 = 0; k0 < K; k0 += 16) {
        #pragma unroll
        for (int i = 0; i < 4; i++) {
            As[c][r + 16 * i] = X[(size_t)(m0 + r + 16 * i) * K + k0 + c];
            Bs[c][r + 16 * i] = W[(size_t)(n0 + r + 16 * i) * K + k0 + c];
        }
        __syncthreads();
        #pragma unroll
        for (int k = 0; k < 16; k++) {
            float a[4], b[4];
            #pragma unroll
            for (int i = 0; i < 4; i++) a[i] = As[k][ty * 4 + i];
            #pragma unroll
            for (int j = 0; j < 4; j++) b[j] = Bs[k][tx * 4 + j];
            #pragma unroll
            for (int i = 0; i < 4; i++)
                #pragma unroll
                for (int j = 0; j < 4; j++)
                    acc[i][j] += a[i] * b[j];
        }
        __syncthreads();
    }

    #pragma unroll
    for (int i = 0; i < 4; i++) {
        const int m = m0 + ty * 4 + i;
        #pragma unroll
        for (int j = 0; j < 4; j++) {
            const int n = n0 + tx * 4 + j;
            const float val = acc[i][j] + bias[n];
            if (SPLIT) {
                const int bb = m >> 11;       // m / SS
                const int s  = m & (SS - 1);
                const int h  = n >> 6;        // n / HDim
                const int dd = n & (HDim - 1);
                g_dummy_noop:;
                ((float*)Y)[(((size_t)bb * HH + h) * SS + s) * HDim + dd] = val;
            } else {
                Y[(size_t)m * DD + n] = val;
            }
        }
    }
}

// ---------------------------------------------------------------------------
// Scores: P[z] = (Q[z] @ K[z]^T) * 1/sqrt(HD), per (b,h) slice z
//   Q,K: (S, HD) row-major per z.  P: (S, S) row-major per z.
// ---------------------------------------------------------------------------
__global__ __launch_bounds__(256) void scores_kernel(
    const float* __restrict__ Q, const float* __restrict__ Km,
    float* __restrict__ P)
{
    const int z = blockIdx.z;
    const float* Qz = Q + (size_t)z * SS * HDim;
    const float* Kz = Km + (size_t)z * SS * HDim;
    float* Pz = P + (size_t)z * SS * SS;

    __shared__ float As[16][65];
    __shared__ float Bs[16][65];
    const int tid = threadIdx.x;
    const int tx = tid & 15, ty = tid >> 4;
    const int m0 = blockIdx.y << 6, n0 = blockIdx.x << 6;
    const int c = tid & 15, r = tid >> 4;

    float acc[4][4] = {};

    #pragma unroll
    for (int k0 = 0; k0 < HDim; k0 += 16) {
        #pragma unroll
        for (int i = 0; i < 4; i++) {
            As[c][r + 16 * i] = Qz[(size_t)(m0 + r + 16 * i) * HDim + k0 + c];
            Bs[c][r + 16 * i] = Kz[(size_t)(n0 + r + 16 * i) * HDim + k0 + c];
        }
        __syncthreads();
        #pragma unroll
        for (int k = 0; k < 16; k++) {
            float a[4], b[4];
            #pragma unroll
            for (int i = 0; i < 4; i++) a[i] = As[k][ty * 4 + i];
            #pragma unroll
            for (int j = 0; j < 4; j++) b[j] = Bs[k][tx * 4 + j];
            #pragma unroll
            for (int i = 0; i < 4; i++)
                #pragma unroll
                for (int j = 0; j < 4; j++)
                    acc[i][j] += a[i] * b[j];
        }
        __syncthreads();
    }

    const float scale = 0.125f;  // 1/sqrt(64)
    #pragma unroll
    for (int i = 0; i < 4; i++) {
        const int m = m0 + ty * 4 + i;
        #pragma unroll
        for (int j = 0; j < 4; j++) {
            const int n = n0 + tx * 4 + j;
            Pz[(size_t)m * SS + n] = acc[i][j] * scale;
        }
    }
}

// ---------------------------------------------------------------------------
// Row softmax in-place: one block (256 threads) per row of length SS=2048.
// ---------------------------------------------------------------------------
__global__ __launch_bounds__(256) void softmax_kernel(float* __restrict__ P)
{
    const size_t row = blockIdx.x;
    float* p = P + row * (size_t)SS;
    const int t = threadIdx.x;

    float v[8];
    float mx = -1e30f;
    #pragma unroll
    for (int i = 0; i < 8; i++) {
        v[i] = p[t + 256 * i];
        mx = fmaxf(mx, v[i]);
    }

    __shared__ float red[256];
    red[t] = mx;
    __syncthreads();
    #pragma unroll
    for (int s = 128; s > 0; s >>= 1) {
        if (t < s) red[t] = fmaxf(red[t], red[t + s]);
        __syncthreads();
    }
    mx = red[0];
    __syncthreads();

    float sum = 0.f;
    #pragma unroll
    for (int i = 0; i < 8; i++) {
        v[i] = __expf(v[i] - mx);
        sum += v[i];
    }
    red[t] = sum;
    __syncthreads();
    #pragma unroll
    for (int s = 128; s > 0; s >>= 1) {
        if (t < s) red[t] += red[t + s];
        __syncthreads();
    }
    const float inv = 1.0f / red[0];
    #pragma unroll
    for (int i = 0; i < 8; i++) p[t + 256 * i] = v[i] * inv;
}

// ---------------------------------------------------------------------------
// AV: AO(b, s=q, h*HD+n) = sum_k P[z][q,k] * V[z][k,n]   (GEMM-NN, N=HD=64)
// ---------------------------------------------------------------------------
__global__ __launch_bounds__(256) void av_kernel(
    const float* __restrict__ P, const float* __restrict__ V,
    float* __restrict__ AO)
{
    const int z = blockIdx.y;
    const int b = z / HH, h = z % HH;
    const float* Pz = P + (size_t)z * SS * SS;
    const float* Vz = V + (size_t)z * SS * HDim;

    __shared__ float As[16][65];   // [k][m]
    __shared__ float Bs[16][64];   // [k][n]
    const int tid = threadIdx.x;
    const int tx = tid & 15, ty = tid >> 4;
    const int m0 = blockIdx.x << 6;
    const int c = tid & 15, r = tid >> 4;

    float acc[4][4] = {};

    for (int k0 = 0; k0 < SS; k0 += 16) {
        #pragma unroll
        for (int i = 0; i < 4; i++)
            As[c][r + 16 * i] = Pz[(size_t)(m0 + r + 16 * i) * SS + k0 + c];
        #pragma unroll
        for (int i = 0; i < 4; i++) {
            const int lin = tid + 256 * i;       // 0..1023
            const int kk = lin >> 6, nn = lin & 63;
            Bs[kk][nn] = Vz[(size_t)(k0 + kk) * HDim + nn];
        }
        __syncthreads();
        #pragma unroll
        for (int k = 0; k < 16; k++) {
            float a[4], bb[4];
            #pragma unroll
            for (int i = 0; i < 4; i++) a[i] = As[k][ty * 4 + i];
            #pragma unroll
            for (int j = 0; j < 4; j++) bb[j] = Bs[k][tx * 4 + j];
            #pragma unroll
            for (int i = 0; i < 4; i++)
                #pragma unroll
                for (int j = 0; j < 4; j++)
                    acc[i][j] += a[i] * bb[j];
        }
        __syncthreads();
    }

    #pragma unroll
    for (int i = 0; i < 4; i++) {
        const int m = m0 + ty * 4 + i;           // seq position
        #pragma unroll
        for (int j = 0; j < 4; j++) {
            const int n = tx * 4 + j;            // hd
            AO[((size_t)b * SS + m) * DD + h * HDim + n] = acc[i][j];
        }
    }
}

// ---------------------------------------------------------------------------
// Launch
// ---------------------------------------------------------------------------
extern "C" void kernel_launch(void* const* d_in, const int* in_sizes, int n_in,
                              void* d_out, int out_size)
{
    const float* query = (const float*)d_in[0];
    const float* key_  = (const float*)d_in[1];
    const float* value = (const float*)d_in[2];
    const float* wq = (const float*)d_in[3];
    const float* bq = (const float*)d_in[4];
    const float* wk = (const float*)d_in[5];
    const float* bk = (const float*)d_in[6];
    const float* wv = (const float*)d_in[7];
    const float* bv = (const float*)d_in[8];
    const float* wo = (const float*)d_in[9];
    const float* bo = (const float*)d_in[10];

    float* out = (float*)d_out;                          // (B,S,D)
    float* attnw = out + (size_t)BB * SS * DD;           // (B,H,S,S)

    float *gq, *gk, *gv, *gao;
    cudaGetSymbolAddress((void**)&gq, g_q);
    cudaGetSymbolAddress((void**)&gk, g_k);
    cudaGetSymbolAddress((void**)&gv, g_v);
    cudaGetSymbolAddress((void**)&gao, g_ao);

    const dim3 gproj(DD / 64, (BB * SS) / 64);           // (16, 64)
    proj_kernel<true><<<gproj, 256>>>(query, wq, bq, gq);
    proj_kernel<true><<<gproj, 256>>>(key_, wk, bk, gk);
    proj_kernel<true><<<gproj, 256>>>(value, wv, bv, gv);

    const dim3 gsc(SS / 64, SS / 64, NH);                // (32, 32, 32)
    scores_kernel<<<gsc, 256>>>(gq, gk, attnw);

    softmax_kernel<<<NH * SS, 256>>>(attnw);             // 65536 rows

    const dim3 gav(SS / 64, NH);                         // (32, 32)
    av_kernel<<<gav, 256>>>(attnw, gv, gao);

    proj_kernel<false><<<gproj, 256>>>(gao, wo, bo, out);
}

// round 3
// speedup vs baseline: 2.2761x; 2.2761x over previous
#include <cuda_runtime.h>
#include <cuda_bf16.h>
#include <cstdint>
#include <math.h>

#define BB 2
#define SS 2048
#define DD 1024
#define HH 16
#define HDim 64
#define NHZ (BB*HH)   // 32 (b,h) slices
#define LDA 18        // u32 per smem row (32 bf16 = 16 u32 + 2 pad)

// Scratch (allocation-free)
__device__ float g_q[(size_t)NHZ * SS * HDim];
__device__ float g_k[(size_t)NHZ * SS * HDim];
__device__ float g_v[(size_t)NHZ * SS * HDim];
__device__ float g_ao[(size_t)BB * SS * DD];

// ---------------------------------------------------------------------------
// mma.sync m16n8k16 bf16 (portable tensor path; tcgen05 unavailable on this
// toolchain target)
// ---------------------------------------------------------------------------
__device__ __forceinline__ void mma_bf16(float d[4], const uint32_t a[4], const uint32_t b[2]) {
    asm volatile(
        "mma.sync.aligned.m16n8k16.row.col.f32.bf16.bf16.f32 "
        "{%0,%1,%2,%3}, {%4,%5,%6,%7}, {%8,%9}, {%0,%1,%2,%3};"
        : "+f"(d[0]), "+f"(d[1]), "+f"(d[2]), "+f"(d[3])
        : "r"(a[0]), "r"(a[1]), "r"(a[2]), "r"(a[3]), "r"(b[0]), "r"(b[1]));
}

// fp32 -> (bf16 hi, bf16 lo) split, packing two values into u32 pairs
__device__ __forceinline__ void split_pack(float a, float b, uint32_t& hi, uint32_t& lo) {
    __nv_bfloat16 ah = __float2bfloat16(a);
    __nv_bfloat16 bh = __float2bfloat16(b);
    __nv_bfloat16 al = __float2bfloat16(a - __bfloat162float(ah));
    __nv_bfloat16 bl = __float2bfloat16(b - __bfloat162float(bh));
    hi = (uint32_t)__bfloat16_as_ushort(ah) | ((uint32_t)__bfloat16_as_ushort(bh) << 16);
    lo = (uint32_t)__bfloat16_as_ushort(al) | ((uint32_t)__bfloat16_as_ushort(bl) << 16);
}

// Load 128 rows x 32 fp32 (row-major, stride), split to bf16 hi/lo in smem
__device__ __forceinline__ void load_tile_rm(const float* __restrict__ src, int stride,
                                             uint32_t* __restrict__ hi,
                                             uint32_t* __restrict__ lo, int tid)
{
    const int c4 = tid & 7;     // 8 float4 = 32 floats per row
    const int r0 = tid >> 3;    // 32 rows per pass
    #pragma unroll
    for (int p = 0; p < 4; p++) {
        const int r = r0 + p * 32;
        float4 v = *(const float4*)(src + (size_t)r * stride + c4 * 4);
        uint32_t h0, l0, h1, l1;
        split_pack(v.x, v.y, h0, l0);
        split_pack(v.z, v.w, h1, l1);
        hi[r * LDA + c4 * 2]     = h0;
        hi[r * LDA + c4 * 2 + 1] = h1;
        lo[r * LDA + c4 * 2]     = l0;
        lo[r * LDA + c4 * 2 + 1] = l1;
    }
}

// Load V block [32 k][64 n] (row-major, stride HDim), transpose -> B[n][k] split
__device__ __forceinline__ void load_v_trans(const float* __restrict__ src,
                                             uint32_t* __restrict__ hi,
                                             uint32_t* __restrict__ lo, int tid)
{
    __nv_bfloat16* h16 = (__nv_bfloat16*)hi;
    __nv_bfloat16* l16 = (__nv_bfloat16*)lo;
    const int n = tid & 63;
    const int k0 = tid >> 6;    // 0..3
    #pragma unroll
    for (int p = 0; p < 8; p++) {
        const int k = k0 + p * 4;
        float v = src[(size_t)k * HDim + n];
        __nv_bfloat16 vh = __float2bfloat16(v);
        __nv_bfloat16 vl = __float2bfloat16(v - __bfloat162float(vh));
        h16[n * (LDA * 2) + k] = vh;
        l16[n * (LDA * 2) + k] = vl;
    }
}

// Fragment loads (m16n8k16 thread mapping; kp = k-pair base = ks*8 u32)
__device__ __forceinline__ void lda_frag(const uint32_t* S, int r, int kp, int l, uint32_t a[4]) {
    const uint32_t* p = S + (size_t)(r + (l >> 2)) * LDA + kp + (l & 3);
    a[0] = p[0];
    a[1] = p[8 * LDA];
    a[2] = p[4];
    a[3] = p[8 * LDA + 4];
}
__device__ __forceinline__ void ldb_frag(const uint32_t* S, int n, int kp, int l, uint32_t b[2]) {
    const uint32_t* p = S + (size_t)(n + (l >> 2)) * LDA + kp + (l & 3);
    b[0] = p[0];
    b[1] = p[4];
}

// ---------------------------------------------------------------------------
// Projection: Y = X @ W^T + bias ; M=4096, N=1024, K=1024. Tile 128x128, BK=32.
// 8 warps, warp tile 32x64 (wm = w&3, wn = w>>2).
// ---------------------------------------------------------------------------
template <bool SPLIT>
__global__ __launch_bounds__(256) void proj_mma(
    const float* __restrict__ X, const float* __restrict__ W,
    const float* __restrict__ bias, float* __restrict__ Y)
{
    __shared__ uint32_t Ahi[128 * LDA], Alo[128 * LDA], Bhi[128 * LDA], Blo[128 * LDA];
    const int tid = threadIdx.x, w = tid >> 5, l = tid & 31;
    const int m0 = blockIdx.y << 7, n0 = blockIdx.x << 7;
    const int wm = (w & 3) * 32, wn = (w >> 2) * 64;

    float acc[2][8][4] = {};

    for (int c = 0; c < DD / 32; c++) {
        load_tile_rm(X + (size_t)m0 * DD + c * 32, DD, Ahi, Alo, tid);
        load_tile_rm(W + (size_t)n0 * DD + c * 32, DD, Bhi, Blo, tid);
        __syncthreads();
        #pragma unroll
        for (int ks = 0; ks < 2; ks++) {
            const int kp = ks * 8;
            uint32_t ah[2][4], al[2][4];
            #pragma unroll
            for (int mi = 0; mi < 2; mi++) {
                lda_frag(Ahi, wm + mi * 16, kp, l, ah[mi]);
                lda_frag(Alo, wm + mi * 16, kp, l, al[mi]);
            }
            #pragma unroll
            for (int ni = 0; ni < 8; ni++) {
                uint32_t bh[2], bl[2];
                ldb_frag(Bhi, wn + ni * 8, kp, l, bh);
                ldb_frag(Blo, wn + ni * 8, kp, l, bl);
                #pragma unroll
                for (int mi = 0; mi < 2; mi++) {
                    mma_bf16(acc[mi][ni], ah[mi], bh);
                    mma_bf16(acc[mi][ni], ah[mi], bl);
                    mma_bf16(acc[mi][ni], al[mi], bh);
                }
            }
        }
        __syncthreads();
    }

    #pragma unroll
    for (int mi = 0; mi < 2; mi++) {
        #pragma unroll
        for (int ni = 0; ni < 8; ni++) {
            const int r  = m0 + wm + mi * 16 + (l >> 2);
            const int cc = n0 + wn + ni * 8 + (l & 3) * 2;
            const float b0 = __ldg(bias + cc), b1 = __ldg(bias + cc + 1);
            float2 o0 = make_float2(acc[mi][ni][0] + b0, acc[mi][ni][1] + b1);
            float2 o1 = make_float2(acc[mi][ni][2] + b0, acc[mi][ni][3] + b1);
            if (SPLIT) {
                const int h = cc >> 6, hd = cc & 63;
                const int b_ = r >> 11, s0 = r & (SS - 1), s1 = (r + 8) & (SS - 1);
                *(float2*)(Y + (((size_t)b_ * HH + h) * SS + s0) * HDim + hd) = o0;
                *(float2*)(Y + (((size_t)b_ * HH + h) * SS + s1) * HDim + hd) = o1;
            } else {
                *(float2*)(Y + (size_t)r * DD + cc) = o0;
                *(float2*)(Y + (size_t)(r + 8) * DD + cc) = o1;
            }
        }
    }
}

// ---------------------------------------------------------------------------
// Scores: P[z] = (Q[z] @ K[z]^T) * 0.125 ; per z: M=N=2048, K=64.
// ---------------------------------------------------------------------------
__global__ __launch_bounds__(256) void scores_mma(
    const float* __restrict__ Q, const float* __restrict__ Km, float* __restrict__ P)
{
    __shared__ uint32_t Ahi[128 * LDA], Alo[128 * LDA], Bhi[128 * LDA], Blo[128 * LDA];
    const int tid = threadIdx.x, w = tid >> 5, l = tid & 31;
    const int z = blockIdx.z;
    const int m0 = blockIdx.y << 7, n0 = blockIdx.x << 7;
    const int wm = (w & 3) * 32, wn = (w >> 2) * 64;
    const float* Qz = Q + (size_t)z * SS * HDim;
    const float* Kz = Km + (size_t)z * SS * HDim;

    float acc[2][8][4] = {};

    #pragma unroll
    for (int c = 0; c < 2; c++) {
        load_tile_rm(Qz + (size_t)m0 * HDim + c * 32, HDim, Ahi, Alo, tid);
        load_tile_rm(Kz + (size_t)n0 * HDim + c * 32, HDim, Bhi, Blo, tid);
        __syncthreads();
        #pragma unroll
        for (int ks = 0; ks < 2; ks++) {
            const int kp = ks * 8;
            uint32_t ah[2][4], al[2][4];
            #pragma unroll
            for (int mi = 0; mi < 2; mi++) {
                lda_frag(Ahi, wm + mi * 16, kp, l, ah[mi]);
                lda_frag(Alo, wm + mi * 16, kp, l, al[mi]);
            }
            #pragma unroll
            for (int ni = 0; ni < 8; ni++) {
                uint32_t bh[2], bl[2];
                ldb_frag(Bhi, wn + ni * 8, kp, l, bh);
                ldb_frag(Blo, wn + ni * 8, kp, l, bl);
                #pragma unroll
                for (int mi = 0; mi < 2; mi++) {
                    mma_bf16(acc[mi][ni], ah[mi], bh);
                    mma_bf16(acc[mi][ni], ah[mi], bl);
                    mma_bf16(acc[mi][ni], al[mi], bh);
                }
            }
        }
        __syncthreads();
    }

    float* Pz = P + (size_t)z * SS * SS;
    #pragma unroll
    for (int mi = 0; mi < 2; mi++) {
        #pragma unroll
        for (int ni = 0; ni < 8; ni++) {
            const int r  = m0 + wm + mi * 16 + (l >> 2);
            const int cc = n0 + wn + ni * 8 + (l & 3) * 2;
            float2 o0 = make_float2(acc[mi][ni][0] * 0.125f, acc[mi][ni][1] * 0.125f);
            float2 o1 = make_float2(acc[mi][ni][2] * 0.125f, acc[mi][ni][3] * 0.125f);
            *(float2*)(Pz + (size_t)r * SS + cc) = o0;
            *(float2*)(Pz + (size_t)(r + 8) * SS + cc) = o1;
        }
    }
}

// ---------------------------------------------------------------------------
// AV: AO = P @ V per z ; M=2048, N=64, K=2048. Tile 128x64, BK=32 (64 chunks).
// 8 warps, warp tile 16x64.
// ---------------------------------------------------------------------------
__global__ __launch_bounds__(256) void av_mma(
    const float* __restrict__ P, const float* __restrict__ V, float* __restrict__ AO)
{
    __shared__ uint32_t Ahi[128 * LDA], Alo[128 * LDA], Bhi[64 * LDA], Blo[64 * LDA];
    const int tid = threadIdx.x, w = tid >> 5, l = tid & 31;
    const int z = blockIdx.y;
    const int b = z / HH, h = z % HH;
    const int m0 = blockIdx.x << 7;
    const int wm = w * 16;
    const float* Pz = P + (size_t)z * SS * SS;
    const float* Vz = V + (size_t)z * SS * HDim;

    float acc[8][4] = {};

    for (int c = 0; c < SS / 32; c++) {
        load_tile_rm(Pz + (size_t)m0 * SS + c * 32, SS, Ahi, Alo, tid);
        load_v_trans(Vz + (size_t)c * 32 * HDim, Bhi, Blo, tid);
        __syncthreads();
        #pragma unroll
        for (int ks = 0; ks < 2; ks++) {
            const int kp = ks * 8;
            uint32_t ah[4], al[4];
            lda_frag(Ahi, wm, kp, l, ah);
            lda_frag(Alo, wm, kp, l, al);
            #pragma unroll
            for (int ni = 0; ni < 8; ni++) {
                uint32_t bh[2], bl[2];
                ldb_frag(Bhi, ni * 8, kp, l, bh);
                ldb_frag(Blo, ni * 8, kp, l, bl);
                mma_bf16(acc[ni], ah, bh);
                mma_bf16(acc[ni], ah, bl);
                mma_bf16(acc[ni], al, bh);
            }
        }
        __syncthreads();
    }

    #pragma unroll
    for (int ni = 0; ni < 8; ni++) {
        const int r  = m0 + wm + (l >> 2);
        const int cc = ni * 8 + (l & 3) * 2;
        *(float2*)(AO + ((size_t)b * SS + r) * DD + h * HDim + cc) =
            make_float2(acc[ni][0], acc[ni][1]);
        *(float2*)(AO + ((size_t)b * SS + r + 8) * DD + h * HDim + cc) =
            make_float2(acc[ni][2], acc[ni][3]);
    }
}

// ---------------------------------------------------------------------------
// Row softmax in-place, float4 + shfl reductions. One block per 2048-row.
// ---------------------------------------------------------------------------
__global__ __launch_bounds__(256) void softmax_kernel(float* __restrict__ P)
{
    const size_t row = blockIdx.x;
    float4* p = (float4*)(P + row * (size_t)SS);
    const int t = threadIdx.x;
    float4 a = p[t];
    float4 b = p[t + 256];
    float mx = fmaxf(fmaxf(fmaxf(a.x, a.y), fmaxf(a.z, a.w)),
                     fmaxf(fmaxf(b.x, b.y), fmaxf(b.z, b.w)));
    #pragma unroll
    for (int o = 16; o > 0; o >>= 1) mx = fmaxf(mx, __shfl_xor_sync(0xFFFFFFFFu, mx, o));
    __shared__ float rmax[8], rsum[8];
    if ((t & 31) == 0) rmax[t >> 5] = mx;
    __syncthreads();
    mx = fmaxf(fmaxf(fmaxf(rmax[0], rmax[1]), fmaxf(rmax[2], rmax[3])),
               fmaxf(fmaxf(rmax[4], rmax[5]), fmaxf(rmax[6], rmax[7])));
    a.x = __expf(a.x - mx); a.y = __expf(a.y - mx);
    a.z = __expf(a.z - mx); a.w = __expf(a.w - mx);
    b.x = __expf(b.x - mx); b.y = __expf(b.y - mx);
    b.z = __expf(b.z - mx); b.w = __expf(b.w - mx);
    float s = a.x + a.y + a.z + a.w + b.x + b.y + b.z + b.w;
    #pragma unroll
    for (int o = 16; o > 0; o >>= 1) s += __shfl_xor_sync(0xFFFFFFFFu, s, o);
    if ((t & 31) == 0) rsum[t >> 5] = s;
    __syncthreads();
    s = rsum[0] + rsum[1] + rsum[2] + rsum[3] + rsum[4] + rsum[5] + rsum[6] + rsum[7];
    const float inv = 1.0f / s;
    a.x *= inv; a.y *= inv; a.z *= inv; a.w *= inv;
    b.x *= inv; b.y *= inv; b.z *= inv; b.w *= inv;
    p[t] = a;
    p[t + 256] = b;
}

// ---------------------------------------------------------------------------
// Launch
// ---------------------------------------------------------------------------
extern "C" void kernel_launch(void* const* d_in, const int* in_sizes, int n_in,
                              void* d_out, int out_size)
{
    const float* query = (const float*)d_in[0];
    const float* key_  = (const float*)d_in[1];
    const float* value = (const float*)d_in[2];
    const float* wq = (const float*)d_in[3];
    const float* bq = (const float*)d_in[4];
    const float* wk = (const float*)d_in[5];
    const float* bk = (const float*)d_in[6];
    const float* wv = (const float*)d_in[7];
    const float* bv = (const float*)d_in[8];
    const float* wo = (const float*)d_in[9];
    const float* bo = (const float*)d_in[10];

    float* out = (float*)d_out;                          // (B,S,D)
    float* attnw = out + (size_t)BB * SS * DD;           // (B,H,S,S)

    float *gq, *gk, *gv, *gao;
    cudaGetSymbolAddress((void**)&gq, g_q);
    cudaGetSymbolAddress((void**)&gk, g_k);
    cudaGetSymbolAddress((void**)&gv, g_v);
    cudaGetSymbolAddress((void**)&gao, g_ao);

    const dim3 gproj(DD / 128, (BB * SS) / 128);         // (8, 32)
    proj_mma<true><<<gproj, 256>>>(query, wq, bq, gq);
    proj_mma<true><<<gproj, 256>>>(key_, wk, bk, gk);
    proj_mma<true><<<gproj, 256>>>(value, wv, bv, gv);

    scores_mma<<<dim3(SS / 128, SS / 128, NHZ), 256>>>(gq, gk, attnw);

    softmax_kernel<<<NHZ * SS, 256>>>(attnw);

    av_mma<<<dim3(SS / 128, NHZ), 256>>>(attnw, gv, gao);

    proj_mma<false><<<gproj, 256>>>(gao, wo, bo, out);
}